// round 8
// baseline (speedup 1.0000x reference)
#include <cuda_runtime.h>
#include <cuda_bf16.h>
#include <cuda_fp16.h>
#include <cstdint>

// Problem constants
#define NN   100000
#define EE   1600000
#define NPAD 100096              // 782 * 128 (padded rows; pads stay zero)
#define NCHUNK 98                // ceil(NN / 1024)

// ---------------------------------------------------------------------------
// Device scratch
// ---------------------------------------------------------------------------
__device__ int g_cnt[NN];                     // degree (histogram)
__device__ int g_off[NN];                     // CSR exclusive offsets
__device__ int g_pos[NN];                     // fill cursors
__device__ int g_csr[EE];                     // dst-grouped src indices
__device__ int g_chunksum[NCHUNK];
__device__ __half g_x16[NN * 128];            // fp16 copy of x (edge-gather payload)
__device__ __nv_bfloat16 g_A1hi[NPAD * 256];  // [mean | x] pre-split
__device__ __nv_bfloat16 g_A1lo[NPAD * 256];
__device__ __half g_y16[NPAD * 64];           // y = h@W2_l.T, fp16 (edge-gather payload)
__device__ float  g_y2 [NN * 64];             // y2 = h@W2_r.T, fp32 (per-node term)
// Pre-split weights, [n][k] k-contiguous
__device__ __nv_bfloat16 g_B1hi[128 * 256];
__device__ __nv_bfloat16 g_B1lo[128 * 256];
__device__ __nv_bfloat16 g_B2hi[128 * 128];
__device__ __nv_bfloat16 g_B2lo[128 * 128];

// ---------------------------------------------------------------------------
// Helpers
// ---------------------------------------------------------------------------
__device__ __forceinline__ uint32_t smem_u32(const void* p) {
    uint32_t a;
    asm("{ .reg .u64 t; cvta.to.shared.u64 t, %1; cvt.u32.u64 %0, t; }" : "=r"(a) : "l"(p));
    return a;
}
#define SWZ(o) ((o) ^ (((o) >> 3) & 0x70u))

__device__ __forceinline__ void split2(float v, __nv_bfloat16& h, __nv_bfloat16& l) {
    h = __float2bfloat16(v);
    l = __float2bfloat16(v - __bfloat162float(h));
}
__device__ __forceinline__ uint32_t pack_bf(__nv_bfloat16 a, __nv_bfloat16 b) {
    __nv_bfloat162 t = __halves2bfloat162(a, b);
    return *(uint32_t*)&t;
}

#define LDSM4(r, a) \
    asm volatile("ldmatrix.sync.aligned.m8n8.x4.shared.b16 {%0,%1,%2,%3}, [%4];" \
        : "=r"((r)[0]), "=r"((r)[1]), "=r"((r)[2]), "=r"((r)[3]) : "r"(a))

__device__ __forceinline__ void mma_bf16(float* d, const uint32_t* a, uint32_t b0, uint32_t b1) {
    asm volatile("mma.sync.aligned.m16n8k16.row.col.f32.bf16.bf16.f32 "
                 "{%0,%1,%2,%3}, {%4,%5,%6,%7}, {%8,%9}, {%0,%1,%2,%3};"
                 : "+f"(d[0]), "+f"(d[1]), "+f"(d[2]), "+f"(d[3])
                 : "r"(a[0]), "r"(a[1]), "r"(a[2]), "r"(a[3]), "r"(b0), "r"(b1));
}

__device__ __forceinline__ void cp16(uint32_t s, const void* g) {
    asm volatile("cp.async.cg.shared.global [%0], [%1], 16;" :: "r"(s), "l"(g));
}
#define CP_COMMIT() asm volatile("cp.async.commit_group;" ::: "memory")
template <int N>
__device__ __forceinline__ void cp_wait() {
    asm volatile("cp.async.wait_group %0;" :: "n"(N) : "memory");
}

// ---------------------------------------------------------------------------
// prep_weights + zero degree counters (merged)
// ---------------------------------------------------------------------------
__global__ void prep_weights(const float* __restrict__ W1l, const float* __restrict__ W1r,
                             const float* __restrict__ W2l, const float* __restrict__ W2r) {
    int idx = blockIdx.x * blockDim.x + threadIdx.x;
    int stride = gridDim.x * blockDim.x;
    for (int i = idx; i < NN; i += stride) g_cnt[i] = 0;
    if (idx < 128 * 256) {
        int n = idx >> 8, k = idx & 255;
        float v = (k < 128) ? W1l[n * 128 + k] : W1r[n * 128 + (k - 128)];
        __nv_bfloat16 h, l; split2(v, h, l);
        g_B1hi[idx] = h; g_B1lo[idx] = l;
    }
    int idx2 = idx - 128 * 256;
    if (idx2 >= 0 && idx2 < 128 * 128) {
        int n = idx2 >> 7, k = idx2 & 127;
        float v = (n < 64) ? W2l[n * 128 + k] : W2r[(n - 64) * 128 + k];
        __nv_bfloat16 h, l; split2(v, h, l);
        g_B2hi[idx2] = h; g_B2lo[idx2] = l;
    }
}

// ---------------------------------------------------------------------------
// count_deg (int4) + x -> fp16 conversion (merged, independent loops)
// ---------------------------------------------------------------------------
__global__ void count_conv(const int* __restrict__ ei, const float4* __restrict__ x4) {
    int tid = blockIdx.x * blockDim.x + threadIdx.x;
    int stride = gridDim.x * blockDim.x;
    for (int i = tid; i < NN * 32; i += stride) {
        float4 v = x4[i];
        __half2 a = __floats2half2_rn(v.x, v.y);
        __half2 b = __floats2half2_rn(v.z, v.w);
        uint2 u;
        u.x = *(uint32_t*)&a;
        u.y = *(uint32_t*)&b;
        ((uint2*)g_x16)[i] = u;
    }
    const int4* d4 = (const int4*)(ei + EE);
    for (int e = tid; e < EE / 4; e += stride) {
        int4 d = d4[e];
        atomicAdd(&g_cnt[d.x], 1);
        atomicAdd(&g_cnt[d.y], 1);
        atomicAdd(&g_cnt[d.z], 1);
        atomicAdd(&g_cnt[d.w], 1);
    }
}

__global__ void scan1() {   // grid = NCHUNK, 1024 threads
    __shared__ int wsum[32];
    int c = blockIdx.x, t = threadIdx.x;
    int i = c * 1024 + t;
    int v = (i < NN) ? g_cnt[i] : 0;
    int x = v;
#pragma unroll
    for (int o = 1; o < 32; o <<= 1) {
        int y = __shfl_up_sync(~0u, x, o);
        if ((t & 31) >= o) x += y;
    }
    if ((t & 31) == 31) wsum[t >> 5] = x;
    __syncthreads();
    if (t < 32) {
        int s = wsum[t];
#pragma unroll
        for (int o = 1; o < 32; o <<= 1) {
            int y = __shfl_up_sync(~0u, s, o);
            if (t >= o) s += y;
        }
        wsum[t] = s;
    }
    __syncthreads();
    int base = (t >= 32) ? wsum[(t >> 5) - 1] : 0;
    int incl = x + base;
    if (i < NN) g_off[i] = incl - v;
    if (t == 1023) g_chunksum[c] = incl;
}

// Every block redundantly scans the 98 chunk sums, then applies grid-stride.
__global__ void scan23() {
    __shared__ int excl[128];
    __shared__ int ws[4];
    int t = threadIdx.x;   // 256
    int v = 0, x = 0;
    if (t < 128) {
        v = (t < NCHUNK) ? g_chunksum[t] : 0;
        x = v;
#pragma unroll
        for (int o = 1; o < 32; o <<= 1) {
            int y = __shfl_up_sync(~0u, x, o);
            if ((t & 31) >= o) x += y;
        }
        if ((t & 31) == 31) ws[t >> 5] = x;
    }
    __syncthreads();
    if (t < 4) {
        int s = ws[t];
#pragma unroll
        for (int o = 1; o < 4; o <<= 1) {
            int y = __shfl_up_sync(0xFu, s, o);
            if (t >= o) s += y;
        }
        ws[t] = s;
    }
    __syncthreads();
    if (t < 128) {
        int base = (t >= 32) ? ws[(t >> 5) - 1] : 0;
        excl[t] = x + base - v;
    }
    __syncthreads();
    int tid = blockIdx.x * blockDim.x + t;
    int stride = gridDim.x * blockDim.x;
    for (int i = tid; i < NN; i += stride) {
        int o = g_off[i] + excl[i >> 10];
        g_off[i] = o;
        g_pos[i] = o;
    }
}

__global__ void fill_csr(const int* __restrict__ ei) {
    int tid = blockIdx.x * blockDim.x + threadIdx.x;
    int stride = gridDim.x * blockDim.x;
    const int4* s4 = (const int4*)ei;
    const int4* d4 = (const int4*)(ei + EE);
    for (int e = tid; e < EE / 4; e += stride) {
        int4 d = d4[e];
        int4 s = s4[e];
        g_csr[atomicAdd(&g_pos[d.x], 1)] = s.x;
        g_csr[atomicAdd(&g_pos[d.y], 1)] = s.y;
        g_csr[atomicAdd(&g_pos[d.z], 1)] = s.z;
        g_csr[atomicAdd(&g_pos[d.w], 1)] = s.w;
    }
}

// ---------------------------------------------------------------------------
// gather1: warp per node, lane owns cols [4l, 4l+4).
// Neighbor sums read x fp16 (uint2/lane), accumulate fp32, mean, split ->
// A1 planes cols [0,128). Own row read fp32 exact -> A1 planes cols [128,256).
// ---------------------------------------------------------------------------
__global__ void gather1(const float4* __restrict__ x4) {
    int lane = threadIdx.x & 31;
    int gw = (blockIdx.x * blockDim.x + threadIdx.x) >> 5;
    int nw = (gridDim.x * blockDim.x) >> 5;
    const uint2* __restrict__ xh = (const uint2*)g_x16;   // row = 32 uint2
    for (int i = gw; i < NN; i += nw) {
        int deg = g_cnt[i], start = g_off[i];
        float4 acc = make_float4(0.f, 0.f, 0.f, 0.f);
        int j = 0;
        for (; j + 4 <= deg; j += 4) {
            int s0 = g_csr[start + j], s1 = g_csr[start + j + 1];
            int s2 = g_csr[start + j + 2], s3 = g_csr[start + j + 3];
            uint2 u0 = xh[s0 * 32 + lane];
            uint2 u1 = xh[s1 * 32 + lane];
            uint2 u2 = xh[s2 * 32 + lane];
            uint2 u3 = xh[s3 * 32 + lane];
            float2 a0 = __half22float2(*(__half2*)&u0.x), b0 = __half22float2(*(__half2*)&u0.y);
            float2 a1 = __half22float2(*(__half2*)&u1.x), b1 = __half22float2(*(__half2*)&u1.y);
            float2 a2 = __half22float2(*(__half2*)&u2.x), b2 = __half22float2(*(__half2*)&u2.y);
            float2 a3 = __half22float2(*(__half2*)&u3.x), b3 = __half22float2(*(__half2*)&u3.y);
            acc.x += (a0.x + a1.x) + (a2.x + a3.x);
            acc.y += (a0.y + a1.y) + (a2.y + a3.y);
            acc.z += (b0.x + b1.x) + (b2.x + b3.x);
            acc.w += (b0.y + b1.y) + (b2.y + b3.y);
        }
        for (; j < deg; j++) {
            int s = g_csr[start + j];
            uint2 u = xh[s * 32 + lane];
            float2 a = __half22float2(*(__half2*)&u.x);
            float2 b = __half22float2(*(__half2*)&u.y);
            acc.x += a.x; acc.y += a.y; acc.z += b.x; acc.w += b.y;
        }
        float inv = 1.0f / fmaxf((float)deg, 1.0f);
        acc.x *= inv; acc.y *= inv; acc.z *= inv; acc.w *= inv;
        __nv_bfloat16 h0, h1, h2, h3, l0, l1, l2, l3;
        split2(acc.x, h0, l0); split2(acc.y, h1, l1);
        split2(acc.z, h2, l2); split2(acc.w, h3, l3);
        uint2 uh, ul;
        uh.x = pack_bf(h0, h1); uh.y = pack_bf(h2, h3);
        ul.x = pack_bf(l0, l1); ul.y = pack_bf(l2, l3);
        ((uint2*)g_A1hi)[(size_t)i * 64 + lane] = uh;
        ((uint2*)g_A1lo)[(size_t)i * 64 + lane] = ul;
        float4 xv = x4[i * 32 + lane];      // own row exact fp32
        split2(xv.x, h0, l0); split2(xv.y, h1, l1);
        split2(xv.z, h2, l2); split2(xv.w, h3, l3);
        uh.x = pack_bf(h0, h1); uh.y = pack_bf(h2, h3);
        ul.x = pack_bf(l0, l1); ul.y = pack_bf(l2, l3);
        ((uint2*)g_A1hi)[(size_t)i * 64 + 32 + lane] = uh;
        ((uint2*)g_A1lo)[(size_t)i * 64 + 32 + lane] = ul;
    }
}

// ---------------------------------------------------------------------------
// FUSED layer1+layer2 GEMM (structure unchanged from R7).
// Epilogue 2 now writes y -> fp16 g_y16, y2 -> fp32 g_y2.
// ---------------------------------------------------------------------------
__global__ __launch_bounds__(512, 1)
void gemm_fused(const float* __restrict__ b1) {
    constexpr int CH = 4;
    constexpr int A_HI = 0, A_LO = 16384, B_HI = 32768, B_LO = 49152;
    extern __shared__ char sm[];
    const uint32_t sb = smem_u32(sm);
    const int tid = threadIdx.x, wid = tid >> 5, lane = tid & 31;
    const int rowBase = blockIdx.x * 128;
    const int wm = wid & 3, wn = wid >> 2;
    const int sub = lane >> 3, lr = lane & 7;

    auto load_chunk1 = [&](int c, int buf) {
        const uint32_t bb = sb + buf * 65536;
#pragma unroll
        for (int it = 0; it < 2; it++) {
            int idx = it * 512 + tid;
            int row = idx >> 3, seg = idx & 7;
            uint32_t doff = SWZ((uint32_t)(row * 128 + seg * 16));
            size_t ga = (size_t)(rowBase + row) * 256 + c * 64 + seg * 8;
            cp16(bb + A_HI + doff, g_A1hi + ga);
            cp16(bb + A_LO + doff, g_A1lo + ga);
            size_t gb = (size_t)row * 256 + c * 64 + seg * 8;
            cp16(bb + B_HI + doff, g_B1hi + gb);
            cp16(bb + B_LO + doff, g_B1lo + gb);
        }
    };

    auto load_B2 = [&]() {
#pragma unroll
        for (int it = 0; it < 4; it++) {
            int idx = it * 512 + tid;          // 0..2047
            int cc  = idx >> 10;
            int r   = idx & 1023;
            int row = r >> 3, seg = r & 7;
            uint32_t doff = SWZ((uint32_t)(row * 128 + seg * 16));
            size_t gb = (size_t)row * 128 + cc * 64 + seg * 8;
            cp16(sb + cc * 32768 + doff,         g_B2hi + gb);
            cp16(sb + cc * 32768 + 16384 + doff, g_B2lo + gb);
        }
    };

    float acc[2][4][4];
#pragma unroll
    for (int i = 0; i < 2; i++)
#pragma unroll
        for (int j = 0; j < 4; j++)
#pragma unroll
            for (int r = 0; r < 4; r++) acc[i][j][r] = 0.f;

    load_chunk1(0, 0); CP_COMMIT();

    // ---- Phase 1 ----
    for (int c = 0; c < CH; c++) {
        if (c + 1 < CH) { load_chunk1(c + 1, (c + 1) & 1); CP_COMMIT(); cp_wait<1>(); }
        else            { load_B2(); CP_COMMIT(); cp_wait<1>(); }
        __syncthreads();

        const uint32_t bb = sb + (c & 1) * 65536;
#pragma unroll
        for (int kk = 0; kk < 4; kk++) {
            uint32_t ah[2][4], al[2][4];
#pragma unroll
            for (int mi = 0; mi < 2; mi++) {
                int row = wm * 32 + mi * 16 + (sub & 1) * 8 + lr;
                int kb  = kk * 32 + (sub >> 1) * 16;
                uint32_t off = SWZ((uint32_t)(row * 128 + kb));
                LDSM4(ah[mi], bb + A_HI + off);
                LDSM4(al[mi], bb + A_LO + off);
            }
#pragma unroll
            for (int p = 0; p < 2; p++) {
                int nr = wn * 32 + p * 16 + (sub >> 1) * 8 + lr;
                int kb = kk * 32 + (sub & 1) * 16;
                uint32_t off = SWZ((uint32_t)(nr * 128 + kb));
                uint32_t bh[4], bl[4];
                LDSM4(bh, bb + B_HI + off);
                LDSM4(bl, bb + B_LO + off);
#pragma unroll
                for (int mi = 0; mi < 2; mi++) {
#pragma unroll
                    for (int h = 0; h < 2; h++) {
                        float* d = acc[mi][p * 2 + h];
                        mma_bf16(d, ah[mi], bh[2 * h], bh[2 * h + 1]);
                        mma_bf16(d, al[mi], bh[2 * h], bh[2 * h + 1]);
                        mma_bf16(d, ah[mi], bl[2 * h], bl[2 * h + 1]);
                    }
                }
            }
        }
        __syncthreads();
    }

    cp_wait<0>();   // B2 resident in buf0

    // ---- Epilogue 1: h = relu(acc + b1) -> split bf16 into buf1 ----
    {
#pragma unroll
        for (int mi = 0; mi < 2; mi++) {
#pragma unroll
            for (int p = 0; p < 2; p++) {
#pragma unroll
                for (int h = 0; h < 2; h++) {
                    int col = wn * 32 + p * 16 + h * 8 + 2 * (lane & 3);
                    int cc = col >> 6, kin = col & 63;
                    float* d = acc[mi][p * 2 + h];
#pragma unroll
                    for (int half = 0; half < 2; half++) {
                        int row = wm * 32 + mi * 16 + (lane >> 2) + half * 8;
                        float v0 = fmaxf(d[half * 2 + 0] + b1[col], 0.f);
                        float v1 = fmaxf(d[half * 2 + 1] + b1[col + 1], 0.f);
                        __nv_bfloat16 h0, l0, h1, l1;
                        split2(v0, h0, l0); split2(v1, h1, l1);
                        uint32_t off = SWZ((uint32_t)(row * 128 + kin * 2));
                        *(uint32_t*)(sm + 65536 + cc * 16384 + off)         = pack_bf(h0, h1);
                        *(uint32_t*)(sm + 65536 + 32768 + cc * 16384 + off) = pack_bf(l0, l1);
                    }
                }
            }
        }
    }
    __syncthreads();

    // ---- Phase 2: z = h @ B2 (K=128, 2 chunks, smem-resident) ----
#pragma unroll
    for (int i = 0; i < 2; i++)
#pragma unroll
        for (int j = 0; j < 4; j++)
#pragma unroll
            for (int r = 0; r < 4; r++) acc[i][j][r] = 0.f;

#pragma unroll
    for (int cc = 0; cc < 2; cc++) {
        const uint32_t ahb = sb + 65536 + cc * 16384;
        const uint32_t alb = sb + 65536 + 32768 + cc * 16384;
        const uint32_t bhb = sb + cc * 32768;
        const uint32_t blb = sb + cc * 32768 + 16384;
#pragma unroll
        for (int kk = 0; kk < 4; kk++) {
            uint32_t ah[2][4], al[2][4];
#pragma unroll
            for (int mi = 0; mi < 2; mi++) {
                int row = wm * 32 + mi * 16 + (sub & 1) * 8 + lr;
                int kb  = kk * 32 + (sub >> 1) * 16;
                uint32_t off = SWZ((uint32_t)(row * 128 + kb));
                LDSM4(ah[mi], ahb + off);
                LDSM4(al[mi], alb + off);
            }
#pragma unroll
            for (int p = 0; p < 2; p++) {
                int nr = wn * 32 + p * 16 + (sub >> 1) * 8 + lr;
                int kb = kk * 32 + (sub & 1) * 16;
                uint32_t off = SWZ((uint32_t)(nr * 128 + kb));
                uint32_t bh[4], bl[4];
                LDSM4(bh, bhb + off);
                LDSM4(bl, blb + off);
#pragma unroll
                for (int mi = 0; mi < 2; mi++) {
#pragma unroll
                    for (int h = 0; h < 2; h++) {
                        float* d = acc[mi][p * 2 + h];
                        mma_bf16(d, ah[mi], bh[2 * h], bh[2 * h + 1]);
                        mma_bf16(d, al[mi], bh[2 * h], bh[2 * h + 1]);
                        mma_bf16(d, ah[mi], bl[2 * h], bl[2 * h + 1]);
                    }
                }
            }
        }
    }

    // ---- Epilogue 2: y (cols<64) -> fp16 g_y16, y2 -> fp32 g_y2 ----
#pragma unroll
    for (int mi = 0; mi < 2; mi++) {
        int r0 = rowBase + wm * 32 + mi * 16 + (lane >> 2);
#pragma unroll
        for (int p = 0; p < 2; p++) {
#pragma unroll
            for (int h = 0; h < 2; h++) {
                int col = wn * 32 + p * 16 + h * 8 + 2 * (lane & 3);
                float* d = acc[mi][p * 2 + h];
#pragma unroll
                for (int half = 0; half < 2; half++) {
                    int gr = r0 + half * 8;
                    if (gr < NN) {
                        float v0 = d[half * 2 + 0];
                        float v1 = d[half * 2 + 1];
                        if (col < 64) {
                            __half2 hh = __floats2half2_rn(v0, v1);
                            *(uint32_t*)(g_y16 + (size_t)gr * 64 + col) = *(uint32_t*)&hh;
                        } else {
                            *(float2*)(g_y2 + (size_t)gr * 64 + (col - 64)) = make_float2(v0, v1);
                        }
                    }
                }
            }
        }
    }
}

// ---------------------------------------------------------------------------
// gather2 (+ fused finalize): warp per node, lane owns cols {2l, 2l+1}.
// out[i] = mean_j(y16[src_j]) + b2 + y2[i]
// ---------------------------------------------------------------------------
__global__ void gather2(float* __restrict__ out, const float* __restrict__ b2) {
    int lane = threadIdx.x & 31;
    int gw = (blockIdx.x * blockDim.x + threadIdx.x) >> 5;
    int nw = (gridDim.x * blockDim.x) >> 5;
    const uint32_t* __restrict__ yh = (const uint32_t*)g_y16;  // row = 32 uint32
    for (int i = gw; i < NN; i += nw) {
        int deg = g_cnt[i], start = g_off[i];
        float2 acc = make_float2(0.f, 0.f);
        int j = 0;
        for (; j + 4 <= deg; j += 4) {
            int s0 = g_csr[start + j], s1 = g_csr[start + j + 1];
            int s2 = g_csr[start + j + 2], s3 = g_csr[start + j + 3];
            uint32_t u0 = yh[s0 * 32 + lane];
            uint32_t u1 = yh[s1 * 32 + lane];
            uint32_t u2 = yh[s2 * 32 + lane];
            uint32_t u3 = yh[s3 * 32 + lane];
            float2 v0 = __half22float2(*(__half2*)&u0);
            float2 v1 = __half22float2(*(__half2*)&u1);
            float2 v2 = __half22float2(*(__half2*)&u2);
            float2 v3 = __half22float2(*(__half2*)&u3);
            acc.x += (v0.x + v1.x) + (v2.x + v3.x);
            acc.y += (v0.y + v1.y) + (v2.y + v3.y);
        }
        for (; j < deg; j++) {
            int s = g_csr[start + j];
            uint32_t u = yh[s * 32 + lane];
            float2 v = __half22float2(*(__half2*)&u);
            acc.x += v.x; acc.y += v.y;
        }
        float inv = 1.0f / fmaxf((float)deg, 1.0f);
        float2 y2 = ((const float2*)g_y2)[(size_t)i * 32 + lane];
        float2 bb = ((const float2*)b2)[lane];
        float2 o = make_float2(acc.x * inv + bb.x + y2.x,
                               acc.y * inv + bb.y + y2.y);
        ((float2*)out)[(size_t)i * 32 + lane] = o;
    }
}

// ---------------------------------------------------------------------------
// Launch. Inputs: x, W1_l, W1_r, b1, W2_l, W2_r, b2, edge_index
// ---------------------------------------------------------------------------
extern "C" void kernel_launch(void* const* d_in, const int* in_sizes, int n_in,
                              void* d_out, int out_size) {
    const float* x   = (const float*)d_in[0];
    const float* W1l = (const float*)d_in[1];
    const float* W1r = (const float*)d_in[2];
    const float* b1  = (const float*)d_in[3];
    const float* W2l = (const float*)d_in[4];
    const float* W2r = (const float*)d_in[5];
    const float* b2  = (const float*)d_in[6];
    const int*   ei  = (const int*)d_in[7];
    float* out = (float*)d_out;

    const int SMEM = 2 * 65536;  // 128 KB
    cudaFuncSetAttribute(gemm_fused, cudaFuncAttributeMaxDynamicSharedMemorySize, SMEM);

    const int NBLK = (NN + 127) / 128;  // 782

    prep_weights<<<392, 256>>>(W1l, W1r, W2l, W2r);
    count_conv<<<1024, 256>>>(ei, (const float4*)x);
    scan1<<<NCHUNK, 1024>>>();
    scan23<<<392, 256>>>();
    fill_csr<<<1024, 256>>>(ei);
    gather1<<<2048, 256>>>((const float4*)x);
    gemm_fused<<<NBLK, 512, SMEM>>>(b1);
    gather2<<<2048, 256>>>(out, b2);
}